// round 2
// baseline (speedup 1.0000x reference)
#include <cuda_runtime.h>
#include <cstdint>
#include <cstddef>

// ---------------------------------------------------------------------------
// RelativeMultiHeadAttention (Transformer-XL style), fp32 baseline.
// B=2, Q_LEN=1024, MEM_LEN=1024, K_LEN=2048, D_MODEL=1024, N_HEADS=16, D_HEAD=64
// ---------------------------------------------------------------------------

#define B_SZ      2
#define Q_LEN     1024
#define MEM_LEN   1024
#define K_LEN     2048
#define D_MODEL   1024
#define N_HEADS   16
#define D_HEAD    64

// Scratch (device globals; allocation-free rule)
__device__ float g_Q [(size_t)B_SZ * Q_LEN * D_MODEL];            // q projection (b, i, D)
__device__ float g_K [(size_t)B_SZ * K_LEN * D_MODEL];            // k projection (b, t, D)
__device__ float g_V [(size_t)B_SZ * K_LEN * D_MODEL];            // v projection (b, t, D)
__device__ float g_R [(size_t)K_LEN * D_MODEL];                   // r projection (t, D)
__device__ float g_S [(size_t)B_SZ * N_HEADS * Q_LEN * K_LEN];    // ac scores -> probs (256MB)
__device__ float g_BD[(size_t)B_SZ * N_HEADS * Q_LEN * K_LEN];    // raw bd matrix   (256MB)
__device__ float g_AV[(size_t)B_SZ * Q_LEN * D_MODEL];            // merged attn_vec (b, i, D)

// ---------------------------------------------------------------------------
// Generic 64x64 NN GEMM tile (fp32), 256 threads, BK=16.
// A: tile row base (m0 applied), lda. B: col base (n0 applied), ldb. C: (m0,n0).
// ---------------------------------------------------------------------------
__device__ __forceinline__ void gemm_nn_tile(
    const float* __restrict__ A, int lda,
    const float* __restrict__ B, int ldb,
    float*       __restrict__ C, int ldc,
    int K)
{
    __shared__ float Ast[16][64];   // transposed A tile
    __shared__ float Bs [16][64];

    const int tid = threadIdx.x;
    const int tx  = tid & 15;
    const int ty  = tid >> 4;

    float acc[4][4] = {};

    for (int k0 = 0; k0 < K; k0 += 16) {
        // Load A tile 64x16 (transposed store)
        {
            const int i  = tid >> 2;          // 0..63
            const int kk = (tid & 3) << 2;    // 0,4,8,12
            float4 a = *reinterpret_cast<const float4*>(&A[(size_t)i * lda + k0 + kk]);
            Ast[kk + 0][i] = a.x;
            Ast[kk + 1][i] = a.y;
            Ast[kk + 2][i] = a.z;
            Ast[kk + 3][i] = a.w;
        }
        // Load B tile 16x64
        {
            const int kk = tid >> 4;          // 0..15
            const int j  = (tid & 15) << 2;   // 0..60
            float4 b = *reinterpret_cast<const float4*>(&B[(size_t)(k0 + kk) * ldb + j]);
            *reinterpret_cast<float4*>(&Bs[kk][j]) = b;
        }
        __syncthreads();

#pragma unroll
        for (int kk = 0; kk < 16; kk++) {
            float4 a4 = *reinterpret_cast<const float4*>(&Ast[kk][ty << 2]);
            float4 b4 = *reinterpret_cast<const float4*>(&Bs [kk][tx << 2]);
            float av[4] = {a4.x, a4.y, a4.z, a4.w};
            float bv[4] = {b4.x, b4.y, b4.z, b4.w};
#pragma unroll
            for (int ii = 0; ii < 4; ii++)
#pragma unroll
                for (int jj = 0; jj < 4; jj++)
                    acc[ii][jj] += av[ii] * bv[jj];
        }
        __syncthreads();
    }

#pragma unroll
    for (int ii = 0; ii < 4; ii++) {
        float4 o = make_float4(acc[ii][0], acc[ii][1], acc[ii][2], acc[ii][3]);
        *reinterpret_cast<float4*>(&C[(size_t)((ty << 2) + ii) * ldc + (tx << 2)]) = o;
    }
}

// Plain NN GEMM: C[M,N] = A[M,K] @ B[K,N]
__global__ __launch_bounds__(256)
void gemm_nn_kernel(const float* __restrict__ A, const float* __restrict__ B,
                    float* __restrict__ C, int K, int lda, int ldb, int ldc)
{
    const float* At = A + (size_t)(blockIdx.y * 64) * lda;
    const float* Bt = B + blockIdx.x * 64;
    float*       Ct = C + (size_t)(blockIdx.y * 64) * ldc + blockIdx.x * 64;
    gemm_nn_tile(At, lda, Bt, ldb, Ct, ldc, K);
}

// K/V projection over cat([mem, h]) without materializing cat.
// grid: (D/64, K_LEN/64, B).  Tiles never cross the mem/h boundary (1024 % 64 == 0).
__global__ __launch_bounds__(256)
void proj_kv_kernel(const float* __restrict__ memp, const float* __restrict__ hp,
                    const float* __restrict__ W, float* __restrict__ Out)
{
    const int b  = blockIdx.z;
    const int m0 = blockIdx.y * 64;
    const float* At = (m0 < MEM_LEN)
        ? memp + ((size_t)b * MEM_LEN + m0) * D_MODEL
        : hp   + ((size_t)b * Q_LEN + (m0 - MEM_LEN)) * D_MODEL;
    const float* Bt = W + blockIdx.x * 64;
    float* Ct = Out + ((size_t)b * K_LEN + m0) * D_MODEL + blockIdx.x * 64;
    gemm_nn_tile(At, D_MODEL, Bt, D_MODEL, Ct, D_MODEL, D_MODEL);
}

// ---------------------------------------------------------------------------
// Score kernel (NT GEMM over D_HEAD=64):
//   Out[z, i, j] = sum_d (Qp[b,i,h*64+d] + bias[h,d]) * Kmat[...,j, h*64+d]
// z = b*16+h.  kBatched selects K-proj (per-batch) vs R-proj (shared).
// ---------------------------------------------------------------------------
__global__ __launch_bounds__(256)
void score_kernel(const float* __restrict__ Qp, const float* __restrict__ Kmat,
                  const float* __restrict__ bias, float* __restrict__ Out,
                  int kBatched)
{
    __shared__ float Qs[64][64];   // [d][i]
    __shared__ float Ks[64][64];   // [d][j]

    const int z  = blockIdx.z;
    const int b  = z >> 4;
    const int hh = z & 15;
    const int i0 = blockIdx.y * 64;
    const int j0 = blockIdx.x * 64;

    const float* Abase = Qp + ((size_t)b * Q_LEN + i0) * D_MODEL + hh * D_HEAD;
    const float* Bbase = kBatched
        ? Kmat + ((size_t)b * K_LEN + j0) * D_MODEL + hh * D_HEAD
        : Kmat + (size_t)j0 * D_MODEL + hh * D_HEAD;
    const float* bi = bias + hh * D_HEAD;

    const int tid = threadIdx.x;

#pragma unroll
    for (int rep = 0; rep < 4; rep++) {
        const int lin = tid + rep * 256;   // 0..1023
        const int row = lin >> 4;          // 0..63
        const int c4  = (lin & 15) << 2;   // 0..60
        float4 q = *reinterpret_cast<const float4*>(&Abase[(size_t)row * D_MODEL + c4]);
        float4 bb = *reinterpret_cast<const float4*>(&bi[c4]);
        q.x += bb.x; q.y += bb.y; q.z += bb.z; q.w += bb.w;
        Qs[c4 + 0][row] = q.x; Qs[c4 + 1][row] = q.y;
        Qs[c4 + 2][row] = q.z; Qs[c4 + 3][row] = q.w;

        float4 k = *reinterpret_cast<const float4*>(&Bbase[(size_t)row * D_MODEL + c4]);
        Ks[c4 + 0][row] = k.x; Ks[c4 + 1][row] = k.y;
        Ks[c4 + 2][row] = k.z; Ks[c4 + 3][row] = k.w;
    }
    __syncthreads();

    const int tx = tid & 15;
    const int ty = tid >> 4;
    float acc[4][4] = {};

#pragma unroll 8
    for (int d = 0; d < 64; d++) {
        float4 a4 = *reinterpret_cast<const float4*>(&Qs[d][ty << 2]);
        float4 b4 = *reinterpret_cast<const float4*>(&Ks[d][tx << 2]);
        float av[4] = {a4.x, a4.y, a4.z, a4.w};
        float bv[4] = {b4.x, b4.y, b4.z, b4.w};
#pragma unroll
        for (int ii = 0; ii < 4; ii++)
#pragma unroll
            for (int jj = 0; jj < 4; jj++)
                acc[ii][jj] += av[ii] * bv[jj];
    }

    float* Crow = Out + ((size_t)z * Q_LEN + i0) * K_LEN + j0;
#pragma unroll
    for (int ii = 0; ii < 4; ii++) {
        float4 o = make_float4(acc[ii][0], acc[ii][1], acc[ii][2], acc[ii][3]);
        *reinterpret_cast<float4*>(&Crow[(size_t)((ty << 2) + ii) * K_LEN + (tx << 2)]) = o;
    }
}

// ---------------------------------------------------------------------------
// Fused rel_shift gather + scale + softmax. One row (b,h,i) per block.
// rel_shift(out)[i,j] with d=j-i:
//   d <= 1024 : X[i,   j-i+1023]
//   d == 1025 : 0                  (the zero pad element)
//   d >= 1026 : X[i+1, j-i-1026]   (wraparound; reference has no mask)
// ---------------------------------------------------------------------------
__global__ __launch_bounds__(256)
void softmax_kernel(float* __restrict__ S, const float* __restrict__ BD)
{
    const int row = blockIdx.x;            // 0 .. B*H*Q-1
    const int i   = row & (Q_LEN - 1);
    float* srow = S + (size_t)row * K_LEN;
    const float* x0 = BD + (size_t)row * K_LEN;    // X row i of this (b,h)
    const float* x1 = x0 + K_LEN;                  // X row i+1 (only read when valid)

    const int tid  = threadIdx.x;
    const int lane = tid & 31;
    const int warp = tid >> 5;

    __shared__ float red[8];

    float sc[8];
    float mx = -1e30f;
#pragma unroll
    for (int c = 0; c < 8; c++) {
        const int j = c * 256 + tid;
        const int d = j - i;
        float bdv;
        if (d <= Q_LEN)           bdv = x0[j - i + (Q_LEN - 1)];
        else if (d == Q_LEN + 1)  bdv = 0.0f;
        else                      bdv = x1[j - i - (Q_LEN + 2)];
        const float v = (srow[j] + bdv) * 0.125f;   // 1/sqrt(64)
        sc[c] = v;
        mx = fmaxf(mx, v);
    }
#pragma unroll
    for (int o = 16; o > 0; o >>= 1) mx = fmaxf(mx, __shfl_xor_sync(0xffffffffu, mx, o));
    if (lane == 0) red[warp] = mx;
    __syncthreads();
    float rowmax = red[0];
#pragma unroll
    for (int w = 1; w < 8; w++) rowmax = fmaxf(rowmax, red[w]);
    __syncthreads();

    float sum = 0.0f;
#pragma unroll
    for (int c = 0; c < 8; c++) {
        sc[c] = __expf(sc[c] - rowmax);
        sum += sc[c];
    }
#pragma unroll
    for (int o = 16; o > 0; o >>= 1) sum += __shfl_xor_sync(0xffffffffu, sum, o);
    if (lane == 0) red[warp] = sum;
    __syncthreads();
    float rowsum = 0.0f;
#pragma unroll
    for (int w = 0; w < 8; w++) rowsum += red[w];
    const float inv = 1.0f / rowsum;

#pragma unroll
    for (int c = 0; c < 8; c++) srow[c * 256 + tid] = sc[c] * inv;
}

// attn_prob @ V per (b,h): M=1024, N=64, K=2048. grid (1, 16, 32)
__global__ __launch_bounds__(256)
void av_kernel(const float* __restrict__ S, const float* __restrict__ V,
               float* __restrict__ AV)
{
    const int z  = blockIdx.z;
    const int b  = z >> 4;
    const int hh = z & 15;
    const int m0 = blockIdx.y * 64;
    const float* At = S + ((size_t)z * Q_LEN + m0) * K_LEN;
    const float* Bt = V + (size_t)b * K_LEN * D_MODEL + hh * D_HEAD;
    float* Ct = AV + ((size_t)b * Q_LEN + m0) * D_MODEL + hh * D_HEAD;
    gemm_nn_tile(At, K_LEN, Bt, D_MODEL, Ct, D_MODEL, K_LEN);
}

// ---------------------------------------------------------------------------
extern "C" void kernel_launch(void* const* d_in, const int* in_sizes, int n_in,
                              void* d_out, int out_size)
{
    const float* h_in  = (const float*)d_in[0];
    const float* mem_p = (const float*)d_in[1];
    const float* r_p   = (const float*)d_in[2];
    const float* Wq    = (const float*)d_in[3];
    const float* Wk    = (const float*)d_in[4];
    const float* Wv    = (const float*)d_in[5];
    const float* Wr    = (const float*)d_in[6];
    const float* Wo    = (const float*)d_in[7];
    const float* rwb   = (const float*)d_in[8];
    const float* rrb   = (const float*)d_in[9];
    float* out = (float*)d_out;

    float *Qp, *Kp, *Vp, *Rp, *Sp, *BDp, *AVp;
    cudaGetSymbolAddress((void**)&Qp,  g_Q);
    cudaGetSymbolAddress((void**)&Kp,  g_K);
    cudaGetSymbolAddress((void**)&Vp,  g_V);
    cudaGetSymbolAddress((void**)&Rp,  g_R);
    cudaGetSymbolAddress((void**)&Sp,  g_S);
    cudaGetSymbolAddress((void**)&BDp, g_BD);
    cudaGetSymbolAddress((void**)&AVp, g_AV);

    dim3 blk(256);

    // 1) q = h @ Wq           (B*Q x D) @ (D x D)
    gemm_nn_kernel<<<dim3(D_MODEL / 64, (B_SZ * Q_LEN) / 64), blk>>>(
        h_in, Wq, Qp, D_MODEL, D_MODEL, D_MODEL, D_MODEL);

    // 2) k = cat(mem,h) @ Wk ; 3) v = cat @ Wv
    proj_kv_kernel<<<dim3(D_MODEL / 64, K_LEN / 64, B_SZ), blk>>>(mem_p, h_in, Wk, Kp);
    proj_kv_kernel<<<dim3(D_MODEL / 64, K_LEN / 64, B_SZ), blk>>>(mem_p, h_in, Wv, Vp);

    // 4) r_head = r @ Wr      (K_LEN x D) @ (D x D)
    gemm_nn_kernel<<<dim3(D_MODEL / 64, K_LEN / 64), blk>>>(
        r_p, Wr, Rp, D_MODEL, D_MODEL, D_MODEL, D_MODEL);

    // 5) ac = (q + r_w_bias) . k^T   -> g_S
    score_kernel<<<dim3(K_LEN / 64, Q_LEN / 64, B_SZ * N_HEADS), blk>>>(
        Qp, Kp, rwb, Sp, 1);

    // 6) bd_raw = (q + r_r_bias) . r_head^T -> g_BD
    score_kernel<<<dim3(K_LEN / 64, Q_LEN / 64, B_SZ * N_HEADS), blk>>>(
        Qp, Rp, rrb, BDp, 0);

    // 7) softmax((ac + rel_shift(bd)) / 8) in place on g_S
    softmax_kernel<<<B_SZ * N_HEADS * Q_LEN, blk>>>(Sp, BDp);

    // 8) attn_vec = prob @ v  -> g_AV (merged heads)
    av_kernel<<<dim3(1, Q_LEN / 64, B_SZ * N_HEADS), blk>>>(Sp, Vp, AVp);

    // 9) out = attn_vec @ Wo
    gemm_nn_kernel<<<dim3(D_MODEL / 64, (B_SZ * Q_LEN) / 64), blk>>>(
        AVp, Wo, out, D_MODEL, D_MODEL, D_MODEL, D_MODEL);
}

// round 4
// speedup vs baseline: 2.3361x; 2.3361x over previous
#include <cuda_runtime.h>
#include <cuda_bf16.h>
#include <cstdint>
#include <cstddef>

#define B_SZ 2
#define QL   1024
#define ML   1024
#define KL   2048
#define DM   1024
#define NH   16
#define DH   64

// ============================ helpers =====================================
__device__ __forceinline__ uint32_t smem_u32(const void* p){
    uint32_t a;
    asm("{ .reg .u64 t; cvta.to.shared.u64 t, %1; cvt.u32.u64 %0, t; }" : "=r"(a) : "l"(p));
    return a;
}

#define SWZ(o) ((o) ^ (((o) >> 3) & 0x70))

__device__ __forceinline__ void ldsm_x4(uint32_t& r0, uint32_t& r1, uint32_t& r2,
                                        uint32_t& r3, uint32_t a){
    asm volatile("ldmatrix.sync.aligned.m8n8.x4.shared.b16 {%0,%1,%2,%3},[%4];"
                 : "=r"(r0), "=r"(r1), "=r"(r2), "=r"(r3) : "r"(a));
}
__device__ __forceinline__ void ldsm_x2(uint32_t& r0, uint32_t& r1, uint32_t a){
    asm volatile("ldmatrix.sync.aligned.m8n8.x2.shared.b16 {%0,%1},[%2];"
                 : "=r"(r0), "=r"(r1) : "r"(a));
}
__device__ __forceinline__ void mma16816(float* c, const uint32_t* a, const uint32_t* b){
    asm volatile(
        "mma.sync.aligned.m16n8k16.row.col.f32.bf16.bf16.f32 "
        "{%0,%1,%2,%3},{%4,%5,%6,%7},{%8,%9},{%0,%1,%2,%3};"
        : "+f"(c[0]), "+f"(c[1]), "+f"(c[2]), "+f"(c[3])
        : "r"(a[0]), "r"(a[1]), "r"(a[2]), "r"(a[3]), "r"(b[0]), "r"(b[1]));
}

// ============================ scratch pools ===============================
#define SZ_1M ((size_t)1024 * 1024)
#define SZ_2M ((size_t)2048 * 1024)
#define SZ_4M ((size_t)4096 * 1024)
#define SZ_P  ((size_t)B_SZ * NH * QL * KL)   // 64M elements

constexpr size_t oHSPh = 0,               oHSPl = oHSPh + SZ_2M;
constexpr size_t oMSPh = oHSPl + SZ_2M,   oMSPl = oMSPh + SZ_2M;
constexpr size_t oRSPh = oMSPl + SZ_2M,   oRSPl = oRSPh + SZ_2M;
constexpr size_t oWT   = oRSPl + SZ_2M;                       // 5 x (hi 1M | lo 1M)
constexpr size_t oQWh  = oWT + 10 * SZ_1M, oQWl = oQWh + SZ_2M;
constexpr size_t oQRh  = oQWl + SZ_2M,    oQRl = oQRh + SZ_2M;
constexpr size_t oKh   = oQRl + SZ_2M,    oKl  = oKh + SZ_4M;
constexpr size_t oRHh  = oKl + SZ_4M,     oRHl = oRHh + SZ_2M;
constexpr size_t oVTh  = oRHl + SZ_2M,    oVTl = oVTh + SZ_4M;
constexpr size_t oPh   = oVTl + SZ_4M,    oPl  = oPh + SZ_P;
constexpr size_t oAVh  = oPl + SZ_P,      oAVl = oAVh + SZ_2M;
constexpr size_t BF_TOTAL = oAVl + SZ_2M;

constexpr size_t fQ  = 0;
constexpr size_t fK  = fQ + SZ_2M;
constexpr size_t fV  = fK + SZ_4M;
constexpr size_t fR  = fV + SZ_4M;
constexpr size_t fAV = fR + SZ_2M;
constexpr size_t fS  = fAV + SZ_2M;
constexpr size_t fBD = fS + SZ_P;
constexpr size_t F_TOTAL = fBD + SZ_P;

__device__ __nv_bfloat16 g_bf[BF_TOTAL];
__device__ float         g_f [F_TOTAL];

// ============================ GEMM core (mma.sync) ========================
// C[128, NT] = (Ahi+Alo)[128,K] * (Bhi+Blo)[NT,K]^T, dropping lo*lo.
// smem rows are 128B: [32 hi bf16 | 32 lo bf16] per 32-element K chunk, SW128.
// 8 warps: warp_m = wid&3 (32 rows), warp_n = wid>>2 (NT/2 cols).
template <int NT>
__device__ __forceinline__ void gemm_core(
    const __nv_bfloat16* __restrict__ Ahi, const __nv_bfloat16* __restrict__ Alo, int lda,
    const __nv_bfloat16* __restrict__ Bhi, const __nv_bfloat16* __restrict__ Blo, int ldb,
    float* __restrict__ C, int ldc, int K)
{
    __shared__ __align__(1024) uint8_t sA[128 * 128];
    __shared__ __align__(1024) uint8_t sB[NT * 128];

    const int tid  = threadIdx.x;
    const int wid  = tid >> 5;
    const int lane = tid & 31;
    const int wm   = wid & 3;
    const int wn   = wid >> 2;
    constexpr int WN     = NT / 2;
    constexpr int NTILES = WN / 8;
    constexpr int BSEG   = NT / 32;   // uint4 loads per thread for B tile

    const uint32_t a32 = smem_u32(sA), b32 = smem_u32(sB);

    float acc[2][NTILES][4];
#pragma unroll
    for (int mt = 0; mt < 2; mt++)
#pragma unroll
        for (int nt = 0; nt < NTILES; nt++)
#pragma unroll
            for (int q = 0; q < 4; q++) acc[mt][nt][q] = 0.0f;

    uint4 pa[4], pb[BSEG];
    const int nch = K >> 5;

    auto ldg_chunk = [&](int k0){
#pragma unroll
        for (int i = 0; i < 4; i++){
            int s = tid + (i << 8); int row = s >> 3, j = s & 7;
            const __nv_bfloat16* p = (j < 4)
                ? Ahi + (size_t)row * lda + k0 + j * 8
                : Alo + (size_t)row * lda + k0 + (j - 4) * 8;
            pa[i] = *reinterpret_cast<const uint4*>(p);
        }
#pragma unroll
        for (int i = 0; i < BSEG; i++){
            int s = tid + (i << 8); int row = s >> 3, j = s & 7;
            const __nv_bfloat16* p = (j < 4)
                ? Bhi + (size_t)row * ldb + k0 + j * 8
                : Blo + (size_t)row * ldb + k0 + (j - 4) * 8;
            pb[i] = *reinterpret_cast<const uint4*>(p);
        }
    };

    // Per-lane ldmatrix base offsets (before adding k-chunk byte offset)
    const uint32_t aRowOff0 = (uint32_t)((wm * 32 + (lane & 15)) << 7) + ((lane >> 4) << 4);
    const uint32_t bRowOff  = (uint32_t)((wn * WN + (lane & 7)) << 7) + (((lane >> 3) & 1) << 4);

    ldg_chunk(0);

    for (int c = 0; c < nch; c++){
        // store prefetched chunk to smem (swizzled)
#pragma unroll
        for (int i = 0; i < 4; i++){
            int s = tid + (i << 8);
            uint32_t off = (uint32_t)((s >> 3) << 7) + (uint32_t)((s & 7) << 4);
            *reinterpret_cast<uint4*>(sA + SWZ(off)) = pa[i];
        }
#pragma unroll
        for (int i = 0; i < BSEG; i++){
            int s = tid + (i << 8);
            uint32_t off = (uint32_t)((s >> 3) << 7) + (uint32_t)((s & 7) << 4);
            *reinterpret_cast<uint4*>(sB + SWZ(off)) = pb[i];
        }
        __syncthreads();

        if (c + 1 < nch) ldg_chunk((c + 1) << 5);   // LDG overlaps MMA

#pragma unroll
        for (int kh = 0; kh < 2; kh++){
            const uint32_t hiOff = (uint32_t)(kh << 5);        // 0 or 32
            const uint32_t loOff = hiOff + 64;                 // 64 or 96

            uint32_t ah[2][4], al[2][4];
#pragma unroll
            for (int mt = 0; mt < 2; mt++){
                uint32_t base = aRowOff0 + (uint32_t)(mt << 11);   // +16 rows
                ldsm_x4(ah[mt][0], ah[mt][1], ah[mt][2], ah[mt][3],
                        a32 + SWZ(base + hiOff));
                ldsm_x4(al[mt][0], al[mt][1], al[mt][2], al[mt][3],
                        a32 + SWZ(base + loOff));
            }
            // B-hi pass: hh + lh
#pragma unroll
            for (int nt = 0; nt < NTILES; nt++){
                uint32_t b[2];
                ldsm_x2(b[0], b[1], b32 + SWZ(bRowOff + (uint32_t)(nt << 10) + hiOff));
                mma16816(acc[0][nt], ah[0], b);
                mma16816(acc[1][nt], ah[1], b);
                mma16816(acc[0][nt], al[0], b);
                mma16816(acc[1][nt], al[1], b);
            }
            // B-lo pass: hl
#pragma unroll
            for (int nt = 0; nt < NTILES; nt++){
                uint32_t b[2];
                ldsm_x2(b[0], b[1], b32 + SWZ(bRowOff + (uint32_t)(nt << 10) + loOff));
                mma16816(acc[0][nt], ah[0], b);
                mma16816(acc[1][nt], ah[1], b);
            }
        }
        __syncthreads();
    }

    // epilogue: fp32 stores (2 contiguous floats per fragment half)
    const int r0 = wm * 32 + (lane >> 2);
    const int cc = (lane & 3) * 2;
#pragma unroll
    for (int mt = 0; mt < 2; mt++){
#pragma unroll
        for (int nt = 0; nt < NTILES; nt++){
            const int col = wn * WN + nt * 8 + cc;
            float* p0 = C + (size_t)(r0 + mt * 16) * ldc + col;
            float* p1 = C + (size_t)(r0 + mt * 16 + 8) * ldc + col;
            *reinterpret_cast<float2*>(p0) = make_float2(acc[mt][nt][0], acc[mt][nt][1]);
            *reinterpret_cast<float2*>(p1) = make_float2(acc[mt][nt][2], acc[mt][nt][3]);
        }
    }
}

// ============================ GEMM wrappers ===============================
__global__ __launch_bounds__(256)
void k_proj(const __nv_bfloat16* __restrict__ Ah, const __nv_bfloat16* __restrict__ Al,
            const __nv_bfloat16* __restrict__ Bh, const __nv_bfloat16* __restrict__ Bl,
            float* __restrict__ C)
{
    size_t ao = (size_t)blockIdx.y * 128 * DM;
    size_t bo = (size_t)blockIdx.x * 128 * DM;
    float* Cp = C + (size_t)blockIdx.y * 128 * DM + blockIdx.x * 128;
    gemm_core<128>(Ah + ao, Al + ao, DM, Bh + bo, Bl + bo, DM, Cp, DM, DM);
}

__global__ __launch_bounds__(256)
void k_proj_cat(const __nv_bfloat16* __restrict__ Mh, const __nv_bfloat16* __restrict__ Ml,
                const __nv_bfloat16* __restrict__ Hh, const __nv_bfloat16* __restrict__ Hl,
                const __nv_bfloat16* __restrict__ Bh, const __nv_bfloat16* __restrict__ Bl,
                float* __restrict__ C)
{
    const int b = blockIdx.z, m0 = blockIdx.y * 128;
    const __nv_bfloat16 *Ah, *Al;
    if (m0 < ML){ size_t o = ((size_t)b * ML + m0) * DM; Ah = Mh + o; Al = Ml + o; }
    else        { size_t o = ((size_t)b * QL + (m0 - ML)) * DM; Ah = Hh + o; Al = Hl + o; }
    size_t bo = (size_t)blockIdx.x * 128 * DM;
    float* Cp = C + ((size_t)b * KL + m0) * DM + blockIdx.x * 128;
    gemm_core<128>(Ah, Al, DM, Bh + bo, Bl + bo, DM, Cp, DM, DM);
}

__global__ __launch_bounds__(256)
void k_score(const __nv_bfloat16* __restrict__ Qh, const __nv_bfloat16* __restrict__ Ql,
             const __nv_bfloat16* __restrict__ Kh, const __nv_bfloat16* __restrict__ Kl2,
             float* __restrict__ Sout, int kBat)
{
    const int z = blockIdx.z, b = z >> 4, h = z & 15;
    const int i0 = blockIdx.y * 128, j0 = blockIdx.x * 128;
    size_t ao = ((size_t)(b * QL + i0)) * DM + h * DH;
    size_t bo = kBat ? ((size_t)(b * KL + j0)) * DM + h * DH
                     : (size_t)j0 * DM + h * DH;
    float* Cp = Sout + ((size_t)z * QL + i0) * KL + j0;
    gemm_core<128>(Qh + ao, Ql + ao, DM, Kh + bo, Kl2 + bo, DM, Cp, KL, DH);
}

__global__ __launch_bounds__(256)
void k_av(const __nv_bfloat16* __restrict__ Ph, const __nv_bfloat16* __restrict__ Pl,
          const __nv_bfloat16* __restrict__ Vh, const __nv_bfloat16* __restrict__ Vl,
          float* __restrict__ AV)
{
    const int z = blockIdx.z, b = z >> 4, h = z & 15;
    const int i0 = blockIdx.y * 128;
    size_t ao = ((size_t)z * QL + i0) * KL;
    size_t bo = ((size_t)b * DM + h * DH) * KL;
    float* Cp = AV + ((size_t)(b * QL + i0)) * DM + h * DH;
    gemm_core<64>(Ph + ao, Pl + ao, KL, Vh + bo, Vl + bo, KL, Cp, DM, KL);
}

// ============================ conversions =================================
__device__ __forceinline__ void split1(float x, __nv_bfloat16& h, __nv_bfloat16& l){
    h = __float2bfloat16(x);
    l = __float2bfloat16(x - __bfloat162float(h));
}

__global__ __launch_bounds__(256)
void k_split(const float* __restrict__ x, __nv_bfloat16* __restrict__ h,
             __nv_bfloat16* __restrict__ l, size_t n)
{
    size_t i = ((size_t)blockIdx.x * 256 + threadIdx.x) * 4;
    if (i >= n) return;
    float4 v = *reinterpret_cast<const float4*>(x + i);
    __nv_bfloat16 h0, h1, h2, h3, l0, l1, l2, l3;
    split1(v.x, h0, l0); split1(v.y, h1, l1);
    split1(v.z, h2, l2); split1(v.w, h3, l3);
    *reinterpret_cast<__nv_bfloat162*>(h + i)     = __halves2bfloat162(h0, h1);
    *reinterpret_cast<__nv_bfloat162*>(h + i + 2) = __halves2bfloat162(h2, h3);
    *reinterpret_cast<__nv_bfloat162*>(l + i)     = __halves2bfloat162(l0, l1);
    *reinterpret_cast<__nv_bfloat162*>(l + i + 2) = __halves2bfloat162(l2, l3);
}

__global__ __launch_bounds__(256)
void k_split_qbias(const float* __restrict__ q,
                   const float* __restrict__ b1, const float* __restrict__ b2,
                   __nv_bfloat16* __restrict__ h1, __nv_bfloat16* __restrict__ l1,
                   __nv_bfloat16* __restrict__ h2, __nv_bfloat16* __restrict__ l2,
                   size_t n)
{
    size_t i = ((size_t)blockIdx.x * 256 + threadIdx.x) * 4;
    if (i >= n) return;
    const int col = (int)(i & (DM - 1));
    float4 v = *reinterpret_cast<const float4*>(q + i);
    float4 a = *reinterpret_cast<const float4*>(b1 + col);
    float4 c = *reinterpret_cast<const float4*>(b2 + col);
    __nv_bfloat16 h0, h1b, h2b, h3, l0, l1b, l2b, l3;
    split1(v.x + a.x, h0, l0);  split1(v.y + a.y, h1b, l1b);
    split1(v.z + a.z, h2b, l2b); split1(v.w + a.w, h3, l3);
    *reinterpret_cast<__nv_bfloat162*>(h1 + i)     = __halves2bfloat162(h0, h1b);
    *reinterpret_cast<__nv_bfloat162*>(h1 + i + 2) = __halves2bfloat162(h2b, h3);
    *reinterpret_cast<__nv_bfloat162*>(l1 + i)     = __halves2bfloat162(l0, l1b);
    *reinterpret_cast<__nv_bfloat162*>(l1 + i + 2) = __halves2bfloat162(l2b, l3);
    split1(v.x + c.x, h0, l0);  split1(v.y + c.y, h1b, l1b);
    split1(v.z + c.z, h2b, l2b); split1(v.w + c.w, h3, l3);
    *reinterpret_cast<__nv_bfloat162*>(h2 + i)     = __halves2bfloat162(h0, h1b);
    *reinterpret_cast<__nv_bfloat162*>(h2 + i + 2) = __halves2bfloat162(h2b, h3);
    *reinterpret_cast<__nv_bfloat162*>(l2 + i)     = __halves2bfloat162(l0, l1b);
    *reinterpret_cast<__nv_bfloat162*>(l2 + i + 2) = __halves2bfloat162(l2b, l3);
}

// out[b][c][r] = split(x[b][r][c]) ; grid (C/32, R/32, batch), block (32,8)
__global__ __launch_bounds__(256)
void k_tsplit(const float* __restrict__ x, __nv_bfloat16* __restrict__ th,
              __nv_bfloat16* __restrict__ tl, int R, int C)
{
    __shared__ float t[32][33];
    const int bz = blockIdx.z;
    const float* xb = x + (size_t)bz * R * C;
    __nv_bfloat16* ph = th + (size_t)bz * R * C;
    __nv_bfloat16* pl = tl + (size_t)bz * R * C;
    const int c0 = blockIdx.x * 32, r0 = blockIdx.y * 32;
    const int tx = threadIdx.x, ty = threadIdx.y;
    for (int i = ty; i < 32; i += 8)
        t[i][tx] = xb[(size_t)(r0 + i) * C + c0 + tx];
    __syncthreads();
    for (int i = ty; i < 32; i += 8){
        __nv_bfloat16 h, l; split1(t[tx][i], h, l);
        ph[(size_t)(c0 + i) * R + r0 + tx] = h;
        pl[(size_t)(c0 + i) * R + r0 + tx] = l;
    }
}

// ============================ softmax =====================================
__global__ __launch_bounds__(256)
void k_softmax(const float* __restrict__ S, const float* __restrict__ BD,
               __nv_bfloat16* __restrict__ Ph, __nv_bfloat16* __restrict__ Pl)
{
    const int row = blockIdx.x;
    const int i   = row & (QL - 1);
    const float* srow = S + (size_t)row * KL;
    const float* x0 = BD + (size_t)row * KL;
    const float* x1 = x0 + KL;

    const int tid = threadIdx.x, lane = tid & 31, warp = tid >> 5;
    __shared__ float red[8];

    float sc[8];
    float mx = -1e30f;
#pragma unroll
    for (int c = 0; c < 8; c++){
        const int j = c * 256 + tid;
        const int d = j - i;
        float bdv;
        if (d <= QL)           bdv = x0[j - i + (QL - 1)];
        else if (d == QL + 1)  bdv = 0.0f;
        else                   bdv = x1[j - i - (QL + 2)];
        const float v = (srow[j] + bdv) * 0.125f;
        sc[c] = v;
        mx = fmaxf(mx, v);
    }
#pragma unroll
    for (int o = 16; o > 0; o >>= 1) mx = fmaxf(mx, __shfl_xor_sync(0xffffffffu, mx, o));
    if (lane == 0) red[warp] = mx;
    __syncthreads();
    float rowmax = red[0];
#pragma unroll
    for (int w = 1; w < 8; w++) rowmax = fmaxf(rowmax, red[w]);
    __syncthreads();

    float sum = 0.0f;
#pragma unroll
    for (int c = 0; c < 8; c++){ sc[c] = __expf(sc[c] - rowmax); sum += sc[c]; }
#pragma unroll
    for (int o = 16; o > 0; o >>= 1) sum += __shfl_xor_sync(0xffffffffu, sum, o);
    if (lane == 0) red[warp] = sum;
    __syncthreads();
    float rowsum = 0.0f;
#pragma unroll
    for (int w = 0; w < 8; w++) rowsum += red[w];
    const float inv = 1.0f / rowsum;

    __nv_bfloat16* ph = Ph + (size_t)row * KL;
    __nv_bfloat16* pl = Pl + (size_t)row * KL;
#pragma unroll
    for (int c = 0; c < 8; c++){
        const int j = c * 256 + tid;
        __nv_bfloat16 h, l; split1(sc[c] * inv, h, l);
        ph[j] = h; pl[j] = l;
    }
}

// ============================ launch ======================================
extern "C" void kernel_launch(void* const* d_in, const int* in_sizes, int n_in,
                              void* d_out, int out_size)
{
    const float* h_in  = (const float*)d_in[0];
    const float* mem_p = (const float*)d_in[1];
    const float* r_p   = (const float*)d_in[2];
    const float* W[5]  = { (const float*)d_in[3], (const float*)d_in[4],
                           (const float*)d_in[5], (const float*)d_in[6],
                           (const float*)d_in[7] };   // Wq, Wk, Wv, Wr, Wo
    const float* rwb   = (const float*)d_in[8];
    const float* rrb   = (const float*)d_in[9];
    float* out = (float*)d_out;

    __nv_bfloat16* bf; float* fp;
    cudaGetSymbolAddress((void**)&bf, g_bf);
    cudaGetSymbolAddress((void**)&fp, g_f);

    // 1) split inputs
    k_split<<<2048, 256>>>(h_in,  bf + oHSPh, bf + oHSPl, SZ_2M);
    k_split<<<2048, 256>>>(mem_p, bf + oMSPh, bf + oMSPl, SZ_2M);
    k_split<<<2048, 256>>>(r_p,   bf + oRSPh, bf + oRSPl, SZ_2M);

    // 2) transpose+split weights: Wt[n][k]
    for (int w = 0; w < 5; w++){
        __nv_bfloat16* th = bf + oWT + (size_t)w * 2 * SZ_1M;
        k_tsplit<<<dim3(32, 32, 1), dim3(32, 8)>>>(W[w], th, th + SZ_1M, 1024, 1024);
    }
    const __nv_bfloat16 *wq = bf + oWT,            *wk = bf + oWT + 2 * SZ_1M,
                        *wv = bf + oWT + 4 * SZ_1M, *wr = bf + oWT + 6 * SZ_1M,
                        *wo = bf + oWT + 8 * SZ_1M;

    // 3) projections (mma.sync)
    k_proj<<<dim3(8, 16), 256>>>(bf + oHSPh, bf + oHSPl, wq, wq + SZ_1M, fp + fQ);
    k_proj_cat<<<dim3(8, 16, 2), 256>>>(bf + oMSPh, bf + oMSPl, bf + oHSPh, bf + oHSPl,
                                        wk, wk + SZ_1M, fp + fK);
    k_proj_cat<<<dim3(8, 16, 2), 256>>>(bf + oMSPh, bf + oMSPl, bf + oHSPh, bf + oHSPl,
                                        wv, wv + SZ_1M, fp + fV);
    k_proj<<<dim3(8, 16), 256>>>(bf + oRSPh, bf + oRSPl, wr, wr + SZ_1M, fp + fR);

    // 4) split projections for score/av GEMMs
    k_split_qbias<<<2048, 256>>>(fp + fQ, rwb, rrb,
                                 bf + oQWh, bf + oQWl, bf + oQRh, bf + oQRl, SZ_2M);
    k_split<<<4096, 256>>>(fp + fK, bf + oKh,  bf + oKl,  SZ_4M);
    k_split<<<2048, 256>>>(fp + fR, bf + oRHh, bf + oRHl, SZ_2M);
    k_tsplit<<<dim3(32, 64, 2), dim3(32, 8)>>>(fp + fV, bf + oVTh, bf + oVTl, KL, DM);

    // 5) scores (fp32 out)
    k_score<<<dim3(16, 8, 32), 256>>>(bf + oQWh, bf + oQWl, bf + oKh,  bf + oKl,
                                      fp + fS, 1);
    k_score<<<dim3(16, 8, 32), 256>>>(bf + oQRh, bf + oQRl, bf + oRHh, bf + oRHl,
                                      fp + fBD, 0);

    // 6) fused rel_shift + softmax -> split probs
    k_softmax<<<B_SZ * NH * QL, 256>>>(fp + fS, fp + fBD, bf + oPh, bf + oPl);

    // 7) attn_vec = prob @ v
    k_av<<<dim3(1, 8, 32), 256>>>(bf + oPh, bf + oPl, bf + oVTh, bf + oVTl, fp + fAV);

    // 8) out = attn_vec @ Wo
    k_split<<<2048, 256>>>(fp + fAV, bf + oAVh, bf + oAVl, SZ_2M);
    k_proj<<<dim3(8, 16), 256>>>(bf + oAVh, bf + oAVl, wo, wo + SZ_1M, out);
}